// round 15
// baseline (speedup 1.0000x reference)
#include <cuda_runtime.h>
#include <math.h>

// Problem shapes (fixed by the dataset's setup_inputs)
#define BATCH   2
#define NMAPS   16
#define CH      256
#define HWPIX   4096   // 64*64
#define TDIM    1024
#define CLPIX   256    // pixels per CLUSTER (4 CTAs x 64 channels each)
#define CLSZ    4      // cluster size
#define CHCTA   64     // channels per CTA in the cluster
#define ATHREADS 512
// GEMM kernel tile
#define GPIX    64
#define GTHREADS 512
#define YPITCH  72                      // bank = 8k+8t+nB -> conflict-free B reads
#define APITCH  36                      // bank = lane id  -> conflict-free A reads
#define KCHUNK  32
#define GSMEM_BYTES ((CH * YPITCH + 2 * CH * APITCH) * 4)   // 73728 + 73728 = 147456 B

// Intermediates in device globals (no allocation allowed)
__device__ float g_q[BATCH * CH];          // q = tr @ Wq^T + bq
__device__ float g_qk[BATCH * CH];         // qk = scale * Wk^T q
__device__ float g_y[BATCH * CH * HWPIX];  // softmax-weighted value sum (tf32 bits), 8 MB

// ---------------- tf32 / mma helpers ----------------
__device__ __forceinline__ unsigned f2tf32(float f) {
    unsigned u;
    asm("cvt.rna.tf32.f32 %0, %1;" : "=r"(u) : "f"(f));
    return u;
}
__device__ __forceinline__ void mma_tf32(
    float& d0, float& d1, float& d2, float& d3,
    unsigned a0, unsigned a1, unsigned a2, unsigned a3,
    unsigned b0, unsigned b1)
{
    asm("mma.sync.aligned.m16n8k8.row.col.f32.tf32.tf32.f32 "
        "{%0,%1,%2,%3}, {%4,%5,%6,%7}, {%8,%9}, {%0,%1,%2,%3};"
        : "+f"(d0), "+f"(d1), "+f"(d2), "+f"(d3)
        : "r"(a0), "r"(a1), "r"(a2), "r"(a3), "r"(b0), "r"(b1));
}

// ---------------- cluster helpers ----------------
__device__ __forceinline__ unsigned smem_u32(const void* p) {
    unsigned a;
    asm("{ .reg .u64 t; cvta.to.shared.u64 t, %1; cvt.u32.u64 %0, t; }" : "=r"(a) : "l"(p));
    return a;
}
__device__ __forceinline__ unsigned my_ctarank() {
    unsigned r;
    asm("mov.u32 %0, %%cluster_ctarank;" : "=r"(r));
    return r;
}
__device__ __forceinline__ void st_cluster_f32(unsigned laddr, unsigned rank, float v) {
    unsigned raddr;
    asm volatile("mapa.shared::cluster.u32 %0, %1, %2;" : "=r"(raddr) : "r"(laddr), "r"(rank));
    asm volatile("st.shared::cluster.f32 [%0], %1;" :: "r"(raddr), "f"(v) : "memory");
}
__device__ __forceinline__ void cluster_bar() {
    asm volatile("barrier.cluster.arrive.aligned;" ::: "memory");
    asm volatile("barrier.cluster.wait.aligned;" ::: "memory");
}

// ---------------- cp.async helpers ----------------
__device__ __forceinline__ void cp16(float* dst_smem, const float* src) {
    unsigned d = (unsigned)__cvta_generic_to_shared(dst_smem);
    asm volatile("cp.async.cg.shared.global [%0], [%1], 16;" :: "r"(d), "l"(src));
}
__device__ __forceinline__ void cp_commit() { asm volatile("cp.async.commit_group;" ::: "memory"); }
__device__ __forceinline__ void cp_wait0()  { asm volatile("cp.async.wait_group 0;" ::: "memory"); }
__device__ __forceinline__ void cp_wait1()  { asm volatile("cp.async.wait_group 1;" ::: "memory"); }

// ---------------- Prep A: q[b][o] = tr[b,:]·Wq[o,:] + bq[o] ----------------
__global__ void __launch_bounds__(256) prepA_kernel(
    const float* __restrict__ tr, const float* __restrict__ Wq,
    const float* __restrict__ bq)
{
    const int blk  = blockIdx.x;
    const int tid  = threadIdx.x;
    const int b    = blk >> 5;
    const int lane = tid & 31;
    const int wid  = tid >> 5;
    const int o    = (blk & 31) * 8 + wid;

    const float4* w4 = (const float4*)(Wq + (size_t)o * TDIM);
    const float4* t4 = (const float4*)(tr + (size_t)b * TDIM);
    float a0 = 0.f, a1 = 0.f, a2 = 0.f, a3 = 0.f;
    #pragma unroll
    for (int k = 0; k < 8; k++) {
        float4 w = w4[lane + 32 * k];
        float4 t = t4[lane + 32 * k];
        a0 += w.x * t.x; a1 += w.y * t.y; a2 += w.z * t.z; a3 += w.w * t.w;
    }
    float acc = (a0 + a1) + (a2 + a3);
    #pragma unroll
    for (int off = 16; off > 0; off >>= 1) acc += __shfl_xor_sync(0xffffffffu, acc, off);
    if (lane == 0) g_q[b * CH + o] = acc + bq[o];
}

// ---------------- Prep B: qk[b][c] = scale * sum_o q[b,o]*Wk[o,c] ----------------
__global__ void __launch_bounds__(256) prepB_kernel(const float* __restrict__ Wk)
{
    __shared__ float part[8][32];
    const int b  = blockIdx.y;
    const int c0 = blockIdx.x * 32;
    const int og = threadIdx.x >> 5;
    const int ci = threadIdx.x & 31;
    const int c  = c0 + ci;

    const float* qb = g_q + b * CH;
    float acc = 0.f;
    #pragma unroll 8
    for (int i = 0; i < 32; i++) {
        int o = og * 32 + i;
        acc += qb[o] * Wk[(size_t)o * CH + c];
    }
    part[og][ci] = acc;
    __syncthreads();
    if (threadIdx.x < 32) {
        float s = part[0][ci] + part[1][ci] + part[2][ci] + part[3][ci]
                + part[4][ci] + part[5][ci] + part[6][ci] + part[7][ci];
        g_qk[b * CH + c0 + ci] = s * 0.0625f;   // CH^-0.5
    }
}

// ---------------- Attention kernel (4-CTA cluster, 256-px window, 64 ch/CTA) ----------------
__global__ void __launch_bounds__(ATHREADS) __cluster_dims__(CLSZ, 1, 1)
attn_kernel(const float* __restrict__ xg)
{
    __shared__ float red_s[CLPIX][9];                     // [pixel][cg] partials
    __shared__ float mbox[2][CLSZ][CLPIX];                // score mailboxes (2-slab parity)
    __shared__ __align__(16) float w_s[CLPIX];
    __shared__ __align__(16) float corr_s[CLPIX];
    __shared__ __align__(16) float rsum_s[CLPIX];

    const int tid  = threadIdx.x;
    const int cid  = blockIdx.x >> 2;          // 0..31
    const unsigned r = my_ctarank();           // 0..3
    const int b    = cid >> 4;                 // 0..1
    const int px0  = (cid & 15) * CLPIX;

    // Thread owns channels 64r + 8*cg .. +7 and pixel quad pq (pixels 4pq..4pq+3)
    const int cg = tid >> 6;   // 0..7
    const int pq = tid & 63;   // 0..63

    float rmax_r = -1e30f, rsum_r = 0.f;

    float qkr[8];
    #pragma unroll
    for (int i = 0; i < 8; i++) qkr[i] = g_qk[b * CH + (int)r * CHCTA + cg * 8 + i];

    const float* xb = xg + ((size_t)b * NMAPS * CH + (int)r * CHCTA + cg * 8) * HWPIX
                         + px0 + 4 * pq;

    float4 cur[8], nxt[8];
    #pragma unroll
    for (int i = 0; i < 8; i++) cur[i] = *(const float4*)(xb + (size_t)i * HWPIX);

    float4 yacc[8];
    #pragma unroll
    for (int i = 0; i < 8; i++) yacc[i] = make_float4(0.f, 0.f, 0.f, 0.f);

    const unsigned mb_base = smem_u32(&mbox[0][0][0]);

    #pragma unroll
    for (int m = 0; m < NMAPS; m++) {
        if (m + 1 < NMAPS) {
            const float* p = xb + (size_t)(m + 1) * CH * HWPIX;
            #pragma unroll
            for (int i = 0; i < 8; i++) nxt[i] = *(const float4*)(p + (size_t)i * HWPIX);
        }

        // Phase A: partial scores (4 px, 8 channels)
        float4 ps = make_float4(0.f, 0.f, 0.f, 0.f);
        #pragma unroll
        for (int i = 0; i < 8; i++) {
            ps.x += qkr[i] * cur[i].x;
            ps.y += qkr[i] * cur[i].y;
            ps.z += qkr[i] * cur[i].z;
            ps.w += qkr[i] * cur[i].w;
        }
        red_s[4 * pq + 0][cg] = ps.x;
        red_s[4 * pq + 1][cg] = ps.y;
        red_s[4 * pq + 2][cg] = ps.z;
        red_s[4 * pq + 3][cg] = ps.w;
        __syncthreads();

        const int par = m & 1;
        if (tid < CLPIX) {
            float s = red_s[tid][0] + red_s[tid][1] + red_s[tid][2] + red_s[tid][3]
                    + red_s[tid][4] + red_s[tid][5] + red_s[tid][6] + red_s[tid][7];
            unsigned laddr = mb_base + ((par * CLSZ + (int)r) * CLPIX + tid) * 4;
            #pragma unroll
            for (unsigned t = 0; t < CLSZ; t++) st_cluster_f32(laddr, t, s);
        }
        cluster_bar();

        if (tid < CLPIX) {
            float s = mbox[par][0][tid] + mbox[par][1][tid]
                    + mbox[par][2][tid] + mbox[par][3][tid];
            float nm = fmaxf(rmax_r, s);
            float cr = __expf(rmax_r - nm);
            float w  = __expf(s - nm);
            rsum_r = rsum_r * cr + w;
            rmax_r = nm;
            w_s[tid]    = w;
            corr_s[tid] = cr;
        }
        __syncthreads();

        // Phase B: y = y*corr + w*x
        {
            float4 wv = *(const float4*)&w_s[4 * pq];
            float4 cv = *(const float4*)&corr_s[4 * pq];
            #pragma unroll
            for (int i = 0; i < 8; i++) {
                yacc[i].x = yacc[i].x * cv.x + wv.x * cur[i].x;
                yacc[i].y = yacc[i].y * cv.y + wv.y * cur[i].y;
                yacc[i].z = yacc[i].z * cv.z + wv.z * cur[i].z;
                yacc[i].w = yacc[i].w * cv.w + wv.w * cur[i].w;
            }
        }
        #pragma unroll
        for (int i = 0; i < 8; i++) cur[i] = nxt[i];
    }

    if (tid < CLPIX) rsum_s[tid] = rsum_r;
    __syncthreads();
    {
        float4 rs = *(const float4*)&rsum_s[4 * pq];
        float4 inv = make_float4(1.f / rs.x, 1.f / rs.y, 1.f / rs.z, 1.f / rs.w);
        #pragma unroll
        for (int i = 0; i < 8; i++) {
            int ch = (int)r * CHCTA + cg * 8 + i;
            float4 tv = make_float4(
                __uint_as_float(f2tf32(yacc[i].x * inv.x)),
                __uint_as_float(f2tf32(yacc[i].y * inv.y)),
                __uint_as_float(f2tf32(yacc[i].z * inv.z)),
                __uint_as_float(f2tf32(yacc[i].w * inv.w)));
            *(float4*)&g_y[((size_t)b * CH + ch) * HWPIX + px0 + 4 * pq] = tv;
        }
    }
}

// ---------------- GEMM v6: out[o,p] = sum_c Wv[o,c]*y[c,p] + bv[o] (tf32 MMA) ----------------
// R13's A-through-smem design (proven: L1% 68->23), but 512 threads / 16 warps:
// warp (wrow, whalf) owns 32 rows x a 32-px half. Per-warp B reuse stays 2,
// total LDS traffic unchanged, warps/SM double 8->16 (occ was the binding
// limit at 12.7%). A fragments shared by warp pairs (wrow, wrow+8).
__global__ void __launch_bounds__(GTHREADS) gemm_kernel(
    const float* __restrict__ Wv, const float* __restrict__ bv,
    float* __restrict__ out)
{
    extern __shared__ float sm[];
    float* ysh = sm;                       // [CH][YPITCH]
    float* ash = sm + CH * YPITCH;         // [2][CH][APITCH]

    const int tid  = threadIdx.x;
    const int b    = blockIdx.x >> 6;          // 0..1
    const int pix0 = (blockIdx.x & 63) * GPIX;

    // stage y tile [256 ch x 64 px] (group: y)
    #pragma unroll
    for (int k = 0; k < 8; k++) {
        int i4 = tid + k * GTHREADS;       // 0..4095
        int c  = i4 >> 4;
        int q  = i4 & 15;
        cp16(&ysh[c * YPITCH + 4 * q],
             g_y + ((size_t)b * CH + c) * HWPIX + pix0 + 4 * q);
    }
    cp_commit();

    // stage A chunks 0 and 1 (groups: A0, A1). Chunk j = Wv[:, 32j..32j+31].
    #pragma unroll
    for (int s = 0; s < 2; s++) {
        #pragma unroll
        for (int k = 0; k < 4; k++) {
            int i   = tid + k * GTHREADS;  // 0..2047
            int row = i >> 3;
            int seg = i & 7;               // 4-col segment
            cp16(&ash[(size_t)s * CH * APITCH + row * APITCH + 4 * seg],
                 Wv + (size_t)row * CH + s * KCHUNK + 4 * seg);
        }
        cp_commit();
    }

    const int w     = tid >> 5;        // 0..15
    const int wrow  = w & 7;           // row group
    const int whalf = w >> 3;          // pixel half
    const int ph    = whalf * 32;      // pixel offset within tile
    const int L     = tid & 31;
    const int r0    = 32 * wrow + (L >> 2);   // tile0 rows: r0, r0+8; tile1: r0+16, r0+24
    const int cA    = L & 3;
    const int nB    = L >> 2;

    float acc[2][4][4];
    #pragma unroll
    for (int u = 0; u < 2; u++) {
        float b0v = bv[r0 + 16 * u], b1v = bv[r0 + 16 * u + 8];
        #pragma unroll
        for (int t = 0; t < 4; t++) {
            acc[u][t][0] = b0v; acc[u][t][1] = b0v;
            acc[u][t][2] = b1v; acc[u][t][3] = b1v;
        }
    }

    cp_wait1();        // y + A0 complete (A1 may still be in flight)
    __syncthreads();

    #pragma unroll 1
    for (int j = 0; j < 8; j++) {
        const float* ab = ash + (size_t)(j & 1) * CH * APITCH;

        #pragma unroll
        for (int kk = 0; kk < 4; kk++) {
            const int kl = 8 * kk + cA;                // within-chunk col
            const int kg = j * KCHUNK + 8 * kk + cA;   // global k for y

            // A fragments from smem (conflict-free: bank = lane), rna-rounded
            unsigned a00 = f2tf32(ab[(size_t)(r0)      * APITCH + kl]);
            unsigned a01 = f2tf32(ab[(size_t)(r0 + 8)  * APITCH + kl]);
            unsigned a02 = f2tf32(ab[(size_t)(r0)      * APITCH + kl + 4]);
            unsigned a03 = f2tf32(ab[(size_t)(r0 + 8)  * APITCH + kl + 4]);
            unsigned a10 = f2tf32(ab[(size_t)(r0 + 16) * APITCH + kl]);
            unsigned a11 = f2tf32(ab[(size_t)(r0 + 24) * APITCH + kl]);
            unsigned a12 = f2tf32(ab[(size_t)(r0 + 16) * APITCH + kl + 4]);
            unsigned a13 = f2tf32(ab[(size_t)(r0 + 24) * APITCH + kl + 4]);

            #pragma unroll
            for (int t = 0; t < 4; t++) {
                const int col = ph + 8 * t + nB;
                unsigned b0 = __float_as_uint(ysh[(size_t)kg * YPITCH + col]);
                unsigned b1 = __float_as_uint(ysh[(size_t)(kg + 4) * YPITCH + col]);
                mma_tf32(acc[0][t][0], acc[0][t][1], acc[0][t][2], acc[0][t][3],
                         a00, a01, a02, a03, b0, b1);
                mma_tf32(acc[1][t][0], acc[1][t][1], acc[1][t][2], acc[1][t][3],
                         a10, a11, a12, a13, b0, b1);
            }
        }

        __syncthreads();   // everyone done reading buffer j&1
        if (j + 2 < 8) {
            // refill buffer j&1 with chunk j+2
            float* dst = ash + (size_t)(j & 1) * CH * APITCH;
            #pragma unroll
            for (int k = 0; k < 4; k++) {
                int i   = tid + k * GTHREADS;
                int row = i >> 3;
                int seg = i & 7;
                cp16(&dst[row * APITCH + 4 * seg],
                     Wv + (size_t)row * CH + (j + 2) * KCHUNK + 4 * seg);
            }
            cp_commit();
            cp_wait1();    // chunk j+1 complete (j+2 may fly)
            __syncthreads();
        } else if (j + 1 < 8) {
            cp_wait0();    // last pending chunk complete
            __syncthreads();
        }
    }

    #pragma unroll
    for (int u = 0; u < 2; u++) {
        #pragma unroll
        for (int t = 0; t < 4; t++) {
            int px = pix0 + ph + 8 * t + 2 * cA;
            float* d0 = out + ((size_t)b * CH + r0 + 16 * u)     * HWPIX + px;
            float* d1 = out + ((size_t)b * CH + r0 + 16 * u + 8) * HWPIX + px;
            *(float2*)d0 = make_float2(acc[u][t][0], acc[u][t][1]);
            *(float2*)d1 = make_float2(acc[u][t][2], acc[u][t][3]);
        }
    }
}

extern "C" void kernel_launch(void* const* d_in, const int* in_sizes, int n_in,
                              void* d_out, int out_size)
{
    const float* tr = (const float*)d_in[0];   // [B, T]
    const float* x  = (const float*)d_in[1];   // [B, M, C, H, W]
    const float* Wq = (const float*)d_in[2];   // [C, T]
    const float* bq = (const float*)d_in[3];   // [C]
    const float* Wk = (const float*)d_in[4];   // [C, C]
    // d_in[5] = bk: constant across the softmax axis -> cancels, unused
    const float* Wv = (const float*)d_in[6];   // [C, C]
    const float* bv = (const float*)d_in[7];   // [C]
    float* out = (float*)d_out;                // [B, C, H, W]

    (void)in_sizes; (void)n_in; (void)out_size;

    cudaFuncSetAttribute(gemm_kernel, cudaFuncAttributeMaxDynamicSharedMemorySize, GSMEM_BYTES);

    prepA_kernel<<<64, 256>>>(tr, Wq, bq);
    prepB_kernel<<<dim3(8, BATCH), 256>>>(Wk);
    attn_kernel<<<BATCH * (HWPIX / CLPIX) * CLSZ, ATHREADS>>>(x);
    gemm_kernel<<<BATCH * (HWPIX / GPIX), GTHREADS, GSMEM_BYTES>>>(Wv, bv, out);
}

// round 16
// speedup vs baseline: 1.1238x; 1.1238x over previous
#include <cuda_runtime.h>
#include <math.h>

// Problem shapes (fixed by the dataset's setup_inputs)
#define BATCH   2
#define NMAPS   16
#define CH      256
#define HWPIX   4096   // 64*64
#define TDIM    1024
#define CLPIX   256    // pixels per CLUSTER (4 CTAs x 64 channels each)
#define CLSZ    4      // cluster size
#define CHCTA   64     // channels per CTA in the cluster
#define ATHREADS 512
// GEMM kernel tile (R13 proven config)
#define GPIX    64
#define GTHREADS 256
#define YPITCH  72                      // bank = 8k+8t+nB -> conflict-free B reads
#define APITCH  36                      // bank = lane id  -> conflict-free A reads
#define KCHUNK  32
#define GSMEM_BYTES ((CH * YPITCH + 2 * CH * APITCH) * 4)   // 147456 B

#define MBOX_TX (CLSZ * CLPIX * 4)      // 4096 bytes of incoming scores per slab

// Intermediates in device globals (no allocation allowed)
__device__ float g_q[BATCH * CH];          // q = tr @ Wq^T + bq
__device__ float g_qk[BATCH * CH];         // qk = scale * Wk^T q
__device__ float g_y[BATCH * CH * HWPIX];  // softmax-weighted value sum (tf32 bits), 8 MB

// ---------------- tf32 / mma helpers ----------------
__device__ __forceinline__ unsigned f2tf32(float f) {
    unsigned u;
    asm("cvt.rna.tf32.f32 %0, %1;" : "=r"(u) : "f"(f));
    return u;
}
__device__ __forceinline__ void mma_tf32(
    float& d0, float& d1, float& d2, float& d3,
    unsigned a0, unsigned a1, unsigned a2, unsigned a3,
    unsigned b0, unsigned b1)
{
    asm("mma.sync.aligned.m16n8k8.row.col.f32.tf32.tf32.f32 "
        "{%0,%1,%2,%3}, {%4,%5,%6,%7}, {%8,%9}, {%0,%1,%2,%3};"
        : "+f"(d0), "+f"(d1), "+f"(d2), "+f"(d3)
        : "r"(a0), "r"(a1), "r"(a2), "r"(a3), "r"(b0), "r"(b1));
}

// ---------------- cluster helpers ----------------
__device__ __forceinline__ unsigned smem_u32(const void* p) {
    unsigned a;
    asm("{ .reg .u64 t; cvta.to.shared.u64 t, %1; cvt.u32.u64 %0, t; }" : "=r"(a) : "l"(p));
    return a;
}
__device__ __forceinline__ unsigned my_ctarank() {
    unsigned r;
    asm("mov.u32 %0, %%cluster_ctarank;" : "=r"(r));
    return r;
}
__device__ __forceinline__ unsigned mapa_rank(unsigned laddr, unsigned rank) {
    unsigned raddr;
    asm("mapa.shared::cluster.u32 %0, %1, %2;" : "=r"(raddr) : "r"(laddr), "r"(rank));
    return raddr;
}
// scalar DSMEM store whose completion feeds the destination CTA's mbarrier tx count
__device__ __forceinline__ void st_async_u32(unsigned raddr, unsigned val, unsigned rmbar) {
    asm volatile(
        "st.async.shared::cluster.mbarrier::complete_tx::bytes.u32 [%0], %1, [%2];"
        :: "r"(raddr), "r"(val), "r"(rmbar) : "memory");
}
__device__ __forceinline__ void mbar_init(unsigned mbar, unsigned count) {
    asm volatile("mbarrier.init.shared.b64 [%0], %1;" :: "r"(mbar), "r"(count) : "memory");
}
__device__ __forceinline__ void mbar_arrive_expect_tx(unsigned mbar, unsigned bytes) {
    asm volatile("mbarrier.arrive.expect_tx.shared.b64 _, [%0], %1;"
                 :: "r"(mbar), "r"(bytes) : "memory");
}
__device__ __forceinline__ void mbar_wait_parity_cluster(unsigned mbar, unsigned parity) {
    asm volatile(
        "{\n\t"
        ".reg .pred P;\n\t"
        "WAIT_%=:\n\t"
        "mbarrier.try_wait.parity.acquire.cluster.shared::cta.b64 P, [%0], %1, 0x989680;\n\t"
        "@P bra.uni DONE_%=;\n\t"
        "bra.uni WAIT_%=;\n\t"
        "DONE_%=:\n\t"
        "}"
        :: "r"(mbar), "r"(parity) : "memory");
}
__device__ __forceinline__ void cluster_bar() {
    asm volatile("barrier.cluster.arrive.aligned;" ::: "memory");
    asm volatile("barrier.cluster.wait.aligned;" ::: "memory");
}

// ---------------- cp.async helpers ----------------
__device__ __forceinline__ void cp16(float* dst_smem, const float* src) {
    unsigned d = (unsigned)__cvta_generic_to_shared(dst_smem);
    asm volatile("cp.async.cg.shared.global [%0], [%1], 16;" :: "r"(d), "l"(src));
}
__device__ __forceinline__ void cp_commit() { asm volatile("cp.async.commit_group;" ::: "memory"); }
__device__ __forceinline__ void cp_wait0()  { asm volatile("cp.async.wait_group 0;" ::: "memory"); }
__device__ __forceinline__ void cp_wait1()  { asm volatile("cp.async.wait_group 1;" ::: "memory"); }

// ---------------- Prep A: q[b][o] = tr[b,:]·Wq[o,:] + bq[o] ----------------
__global__ void __launch_bounds__(256) prepA_kernel(
    const float* __restrict__ tr, const float* __restrict__ Wq,
    const float* __restrict__ bq)
{
    const int blk  = blockIdx.x;
    const int tid  = threadIdx.x;
    const int b    = blk >> 5;
    const int lane = tid & 31;
    const int wid  = tid >> 5;
    const int o    = (blk & 31) * 8 + wid;

    const float4* w4 = (const float4*)(Wq + (size_t)o * TDIM);
    const float4* t4 = (const float4*)(tr + (size_t)b * TDIM);
    float a0 = 0.f, a1 = 0.f, a2 = 0.f, a3 = 0.f;
    #pragma unroll
    for (int k = 0; k < 8; k++) {
        float4 w = w4[lane + 32 * k];
        float4 t = t4[lane + 32 * k];
        a0 += w.x * t.x; a1 += w.y * t.y; a2 += w.z * t.z; a3 += w.w * t.w;
    }
    float acc = (a0 + a1) + (a2 + a3);
    #pragma unroll
    for (int off = 16; off > 0; off >>= 1) acc += __shfl_xor_sync(0xffffffffu, acc, off);
    if (lane == 0) g_q[b * CH + o] = acc + bq[o];
}

// ---------------- Prep B: qk[b][c] = scale * sum_o q[b,o]*Wk[o,c] ----------------
__global__ void __launch_bounds__(256) prepB_kernel(const float* __restrict__ Wk)
{
    __shared__ float part[8][32];
    const int b  = blockIdx.y;
    const int c0 = blockIdx.x * 32;
    const int og = threadIdx.x >> 5;
    const int ci = threadIdx.x & 31;
    const int c  = c0 + ci;

    const float* qb = g_q + b * CH;
    float acc = 0.f;
    #pragma unroll 8
    for (int i = 0; i < 32; i++) {
        int o = og * 32 + i;
        acc += qb[o] * Wk[(size_t)o * CH + c];
    }
    part[og][ci] = acc;
    __syncthreads();
    if (threadIdx.x < 32) {
        float s = part[0][ci] + part[1][ci] + part[2][ci] + part[3][ci]
                + part[4][ci] + part[5][ci] + part[6][ci] + part[7][ci];
        g_qk[b * CH + c0 + ci] = s * 0.0625f;   // CH^-0.5
    }
}

// ---------------- Attention kernel (4-CTA cluster, st.async mbarrier exchange) ----------------
__global__ void __launch_bounds__(ATHREADS) __cluster_dims__(CLSZ, 1, 1)
attn_kernel(const float* __restrict__ xg)
{
    __shared__ float red_s[CLPIX][9];                     // [pixel][cg] partials
    __shared__ float mbox[2][CLSZ][CLPIX];                // score mailboxes (2-slab parity)
    __shared__ __align__(16) float w_s[CLPIX];
    __shared__ __align__(16) float corr_s[CLPIX];
    __shared__ __align__(16) float rsum_s[CLPIX];
    __shared__ __align__(8) unsigned long long mbars[2];  // per-parity transaction barriers

    const int tid  = threadIdx.x;
    const int cid  = blockIdx.x >> 2;          // 0..31
    const unsigned r = my_ctarank();           // 0..3
    const int b    = cid >> 4;                 // 0..1
    const int px0  = (cid & 15) * CLPIX;

    // Thread owns channels 64r + 8*cg .. +7 and pixel quad pq (pixels 4pq..4pq+3)
    const int cg = tid >> 6;   // 0..7
    const int pq = tid & 63;   // 0..63

    float rmax_r = -1e30f, rsum_r = 0.f;

    const unsigned mb_base   = smem_u32(&mbox[0][0][0]);
    const unsigned mbar_base = smem_u32(&mbars[0]);

    if (tid == 0) {
        mbar_init(mbar_base,     1);   // 1 arrival (tid0's expect_tx) + MBOX_TX bytes per phase
        mbar_init(mbar_base + 8, 1);
    }
    __syncthreads();
    cluster_bar();   // all mbarriers live before any st.async targets them

    // per-rank remote base addresses (hoisted mapa)
    unsigned rmb[CLSZ], rbar[CLSZ];
    #pragma unroll
    for (unsigned t = 0; t < CLSZ; t++) {
        rmb[t]  = mapa_rank(mb_base, t);
        rbar[t] = mapa_rank(mbar_base, t);
    }

    float qkr[8];
    #pragma unroll
    for (int i = 0; i < 8; i++) qkr[i] = g_qk[b * CH + (int)r * CHCTA + cg * 8 + i];

    const float* xb = xg + ((size_t)b * NMAPS * CH + (int)r * CHCTA + cg * 8) * HWPIX
                         + px0 + 4 * pq;

    float4 cur[8], nxt[8];
    #pragma unroll
    for (int i = 0; i < 8; i++) cur[i] = *(const float4*)(xb + (size_t)i * HWPIX);

    float4 yacc[8];
    #pragma unroll
    for (int i = 0; i < 8; i++) yacc[i] = make_float4(0.f, 0.f, 0.f, 0.f);

    #pragma unroll
    for (int m = 0; m < NMAPS; m++) {
        if (m + 1 < NMAPS) {
            const float* p = xb + (size_t)(m + 1) * CH * HWPIX;
            #pragma unroll
            for (int i = 0; i < 8; i++) nxt[i] = *(const float4*)(p + (size_t)i * HWPIX);
        }

        // Phase A: partial scores (4 px, 8 channels)
        float4 ps = make_float4(0.f, 0.f, 0.f, 0.f);
        #pragma unroll
        for (int i = 0; i < 8; i++) {
            ps.x += qkr[i] * cur[i].x;
            ps.y += qkr[i] * cur[i].y;
            ps.z += qkr[i] * cur[i].z;
            ps.w += qkr[i] * cur[i].w;
        }
        red_s[4 * pq + 0][cg] = ps.x;
        red_s[4 * pq + 1][cg] = ps.y;
        red_s[4 * pq + 2][cg] = ps.z;
        red_s[4 * pq + 3][cg] = ps.w;
        __syncthreads();

        const int par    = m & 1;
        const int phase  = (m >> 1) & 1;
        if (tid < CLPIX) {
            float s = red_s[tid][0] + red_s[tid][1] + red_s[tid][2] + red_s[tid][3]
                    + red_s[tid][4] + red_s[tid][5] + red_s[tid][6] + red_s[tid][7];
            // publish s into every CTA's mbox[par][r][tid], completing their mbar tx
            const unsigned off = ((par * CLSZ + (int)r) * CLPIX + tid) * 4;
            const unsigned sv  = __float_as_uint(s);
            #pragma unroll
            for (unsigned t = 0; t < CLSZ; t++)
                st_async_u32(rmb[t] + off, sv, rbar[t] + par * 8);
            if (tid == 0) mbar_arrive_expect_tx(mbar_base + par * 8, MBOX_TX);
            // wait for all 4 CTAs' scores for this slab
            mbar_wait_parity_cluster(mbar_base + par * 8, (unsigned)phase);

            float sf = mbox[par][0][tid] + mbox[par][1][tid]
                     + mbox[par][2][tid] + mbox[par][3][tid];
            float nm = fmaxf(rmax_r, sf);
            float cr = __expf(rmax_r - nm);
            float w  = __expf(sf - nm);
            rsum_r = rsum_r * cr + w;
            rmax_r = nm;
            w_s[tid]    = w;
            corr_s[tid] = cr;
        }
        __syncthreads();

        // Phase B: y = y*corr + w*x
        {
            float4 wv = *(const float4*)&w_s[4 * pq];
            float4 cv = *(const float4*)&corr_s[4 * pq];
            #pragma unroll
            for (int i = 0; i < 8; i++) {
                yacc[i].x = yacc[i].x * cv.x + wv.x * cur[i].x;
                yacc[i].y = yacc[i].y * cv.y + wv.y * cur[i].y;
                yacc[i].z = yacc[i].z * cv.z + wv.z * cur[i].z;
                yacc[i].w = yacc[i].w * cv.w + wv.w * cur[i].w;
            }
        }
        #pragma unroll
        for (int i = 0; i < 8; i++) cur[i] = nxt[i];
    }

    if (tid < CLPIX) rsum_s[tid] = rsum_r;
    __syncthreads();
    {
        float4 rs = *(const float4*)&rsum_s[4 * pq];
        float4 inv = make_float4(1.f / rs.x, 1.f / rs.y, 1.f / rs.z, 1.f / rs.w);
        #pragma unroll
        for (int i = 0; i < 8; i++) {
            int ch = (int)r * CHCTA + cg * 8 + i;
            float4 tv = make_float4(
                __uint_as_float(f2tf32(yacc[i].x * inv.x)),
                __uint_as_float(f2tf32(yacc[i].y * inv.y)),
                __uint_as_float(f2tf32(yacc[i].z * inv.z)),
                __uint_as_float(f2tf32(yacc[i].w * inv.w)));
            *(float4*)&g_y[((size_t)b * CH + ch) * HWPIX + px0 + 4 * pq] = tv;
        }
    }

    // keep all CTAs alive until every peer's in-flight st.async has landed
    cluster_bar();
}

// ---------------- GEMM (R13 proven): out[o,p] = sum_c Wv[o,c]*y[c,p] + bv[o] ----------------
// 256 threads / 8 warps; warp = 32 rows x 64 px (B reuse 2). A (Wv) staged
// through smem in double-buffered 32-k chunks via cp.async (L1% 68->23 win).
__global__ void __launch_bounds__(GTHREADS) gemm_kernel(
    const float* __restrict__ Wv, const float* __restrict__ bv,
    float* __restrict__ out)
{
    extern __shared__ float sm[];
    float* ysh = sm;                       // [CH][YPITCH]
    float* ash = sm + CH * YPITCH;         // [2][CH][APITCH]

    const int tid  = threadIdx.x;
    const int b    = blockIdx.x >> 6;          // 0..1
    const int pix0 = (blockIdx.x & 63) * GPIX;

    // stage y tile [256 ch x 64 px] (group: y)
    #pragma unroll
    for (int k = 0; k < 16; k++) {
        int i4 = tid + k * GTHREADS;       // 0..4095
        int c  = i4 >> 4;
        int q  = i4 & 15;
        cp16(&ysh[c * YPITCH + 4 * q],
             g_y + ((size_t)b * CH + c) * HWPIX + pix0 + 4 * q);
    }
    cp_commit();

    // stage A chunks 0 and 1 (groups: A0, A1). Chunk j = Wv[:, 32j..32j+31].
    #pragma unroll
    for (int s = 0; s < 2; s++) {
        #pragma unroll
        for (int k = 0; k < 8; k++) {
            int i   = tid + k * GTHREADS;  // 0..2047
            int row = i >> 3;
            int seg = i & 7;               // 4-col segment
            cp16(&ash[(size_t)s * CH * APITCH + row * APITCH + 4 * seg],
                 Wv + (size_t)row * CH + s * KCHUNK + 4 * seg);
        }
        cp_commit();
    }

    const int w  = tid >> 5;        // 0..7
    const int L  = tid & 31;
    const int r0 = 32 * w + (L >> 2);   // tile0 rows: r0, r0+8; tile1: r0+16, r0+24
    const int cA = L & 3;
    const int nB = L >> 2;

    float acc[2][8][4];
    #pragma unroll
    for (int u = 0; u < 2; u++) {
        float b0v = bv[r0 + 16 * u], b1v = bv[r0 + 16 * u + 8];
        #pragma unroll
        for (int t = 0; t < 8; t++) {
            acc[u][t][0] = b0v; acc[u][t][1] = b0v;
            acc[u][t][2] = b1v; acc[u][t][3] = b1v;
        }
    }

    cp_wait1();        // y + A0 complete (A1 may still be in flight)
    __syncthreads();

    #pragma unroll 1
    for (int j = 0; j < 8; j++) {
        const float* ab = ash + (size_t)(j & 1) * CH * APITCH;

        #pragma unroll
        for (int kk = 0; kk < 4; kk++) {
            const int kl = 8 * kk + cA;                // within-chunk col
            const int kg = j * KCHUNK + 8 * kk + cA;   // global k for y

            unsigned a00 = f2tf32(ab[(size_t)(r0)      * APITCH + kl]);
            unsigned a01 = f2tf32(ab[(size_t)(r0 + 8)  * APITCH + kl]);
            unsigned a02 = f2tf32(ab[(size_t)(r0)      * APITCH + kl + 4]);
            unsigned a03 = f2tf32(ab[(size_t)(r0 + 8)  * APITCH + kl + 4]);
            unsigned a10 = f2tf32(ab[(size_t)(r0 + 16) * APITCH + kl]);
            unsigned a11 = f2tf32(ab[(size_t)(r0 + 24) * APITCH + kl]);
            unsigned a12 = f2tf32(ab[(size_t)(r0 + 16) * APITCH + kl + 4]);
            unsigned a13 = f2tf32(ab[(size_t)(r0 + 24) * APITCH + kl + 4]);

            #pragma unroll
            for (int t = 0; t < 8; t++) {
                unsigned b0 = __float_as_uint(ysh[(size_t)kg * YPITCH + 8 * t + nB]);
                unsigned b1 = __float_as_uint(ysh[(size_t)(kg + 4) * YPITCH + 8 * t + nB]);
                mma_tf32(acc[0][t][0], acc[0][t][1], acc[0][t][2], acc[0][t][3],
                         a00, a01, a02, a03, b0, b1);
                mma_tf32(acc[1][t][0], acc[1][t][1], acc[1][t][2], acc[1][t][3],
                         a10, a11, a12, a13, b0, b1);
            }
        }

        __syncthreads();   // everyone done reading buffer j&1
        if (j + 2 < 8) {
            float* dst = ash + (size_t)(j & 1) * CH * APITCH;
            #pragma unroll
            for (int k = 0; k < 8; k++) {
                int i   = tid + k * GTHREADS;
                int row = i >> 3;
                int seg = i & 7;
                cp16(&dst[row * APITCH + 4 * seg],
                     Wv + (size_t)row * CH + (j + 2) * KCHUNK + 4 * seg);
            }
            cp_commit();
            cp_wait1();    // chunk j+1 complete (j+2 may fly)
            __syncthreads();
        } else if (j + 1 < 8) {
            cp_wait0();    // last pending chunk complete
            __syncthreads();
        }
    }

    #pragma unroll
    for (int u = 0; u < 2; u++) {
        #pragma unroll
        for (int t = 0; t < 8; t++) {
            int px = pix0 + 8 * t + 2 * cA;
            float* d0 = out + ((size_t)b * CH + r0 + 16 * u)     * HWPIX + px;
            float* d1 = out + ((size_t)b * CH + r0 + 16 * u + 8) * HWPIX + px;
            *(float2*)d0 = make_float2(acc[u][t][0], acc[u][t][1]);
            *(float2*)d1 = make_float2(acc[u][t][2], acc[u][t][3]);
        }
    }
}

extern "C" void kernel_launch(void* const* d_in, const int* in_sizes, int n_in,
                              void* d_out, int out_size)
{
    const float* tr = (const float*)d_in[0];   // [B, T]
    const float* x  = (const float*)d_in[1];   // [B, M, C, H, W]
    const float* Wq = (const float*)d_in[2];   // [C, T]
    const float* bq = (const float*)d_in[3];   // [C]
    const float* Wk = (const float*)d_in[4];   // [C, C]
    // d_in[5] = bk: constant across the softmax axis -> cancels, unused
    const float* Wv = (const float*)d_in[6];   // [C, C]
    const float* bv = (const float*)d_in[7];   // [C]
    float* out = (float*)d_out;                // [B, C, H, W]

    (void)in_sizes; (void)n_in; (void)out_size;

    cudaFuncSetAttribute(gemm_kernel, cudaFuncAttributeMaxDynamicSharedMemorySize, GSMEM_BYTES);

    prepA_kernel<<<64, 256>>>(tr, Wq, bq);
    prepB_kernel<<<dim3(8, BATCH), 256>>>(Wk);
    attn_kernel<<<BATCH * (HWPIX / CLPIX) * CLSZ, ATHREADS>>>(x);
    gemm_kernel<<<BATCH * (HWPIX / GPIX), GTHREADS, GSMEM_BYTES>>>(Wv, bv, out);
}